// round 8
// baseline (speedup 1.0000x reference)
#include <cuda_runtime.h>
#include <cstdint>

#define W 8192
#define H 2048
#define NPIX (W * H)
#define THREADS 256
#define PX_PER_BLOCK 2048
#define CHUNKS (PX_PER_BLOCK / THREADS)          // 8
#define NBLOCKS (NPIX / PX_PER_BLOCK)            // 8192
#define IMG_BYTES_PER_BLOCK (PX_PER_BLOCK * 16)  // 32768
#define OUT_BYTES_PER_BLOCK (PX_PER_BLOCK * 12)  // 24576

#define FOV_SPAN     0.5235987755982988f
#define FOV_ABS_DOWN 0.2617993877991494f
#define TWO_PI       6.283185307179586f
#define PI_F         3.141592653589793f

// Rotation by 256 column steps: delta = 256 * 2*pi/8192 = pi/16
#define ROT_C 0.9807852804032304f
#define ROT_S 0.1950903220161283f

__device__ __forceinline__ uint32_t smem_u32(const void* p) {
    uint32_t a;
    asm("{ .reg .u64 t; cvta.to.shared.u64 t, %1; cvt.u32.u64 %0, t; }"
        : "=r"(a) : "l"(p));
    return a;
}

// Single kernel. Per block (2048 consecutive pixels of one row; 2048 | 8192):
//   1. ONE cp.async.bulk gmem->smem (32 KB image tile)
//   2. sincosf(yaw)/sinf(pitch) computed WHILE the TMA is in flight
//   3. wait; extract all depths to registers; __syncthreads;
//      write xyz back into the SAME smem buffer (reuse: 24 KB of the 32 KB)
//   4. ONE cp.async.bulk smem->gmem (24 KB)
// vs R7: half the blocks -> half the trig, half the TMA ops (each 2x larger),
// half the mbarrier traffic, ~half the waves (smaller end-of-grid drain).
__global__ void __launch_bounds__(THREADS)
proj_to_pointcloud_kernel(const float* __restrict__ img, float* __restrict__ out) {
    __shared__ alignas(128) float s_buf[PX_PER_BLOCK * 4];   // 32 KB, dual-use
    __shared__ alignas(8)   uint64_t s_mbar;

    int t = threadIdx.x;
    long blockBase = (long)blockIdx.x * PX_PER_BLOCK;
    int row = (int)(blockBase >> 13);
    int j0  = (int)(blockBase & (W - 1));
    uint32_t mb = smem_u32(&s_mbar);

    if (t == 0) {
        asm volatile("mbarrier.init.shared.b64 [%0], %1;" :: "r"(mb), "r"(1));
    }
    __syncthreads();

    if (t == 0) {
        asm volatile("mbarrier.arrive.expect_tx.shared.b64 _, [%0], %1;"
                     :: "r"(mb), "r"(IMG_BYTES_PER_BLOCK) : "memory");
        uint32_t dstp = smem_u32(s_buf);
        const float* srcp = img + (blockBase << 2);
        asm volatile(
            "cp.async.bulk.shared::cta.global.mbarrier::complete_tx::bytes "
            "[%0], [%1], %2, [%3];"
            :: "r"(dstp), "l"(srcp), "n"(IMG_BYTES_PER_BLOCK), "r"(mb) : "memory");
    }

    // ---- trig, overlapped with the TMA load ----
    float yaw = (float)(j0 + t) * (TWO_PI / (float)W) - PI_F;
    float s, c;
    sincosf(yaw, &s, &c);
    float pitch = (1.0f - (float)row / (float)H) * FOV_SPAN - FOV_ABS_DOWN;
    float sp = sinf(pitch);

    // ---- wait for image tile ----
    asm volatile(
        "{\n\t"
        ".reg .pred P;\n\t"
        "WAIT_%=:\n\t"
        "mbarrier.try_wait.parity.acquire.cta.shared::cta.b64 P, [%0], %1, 0x989680;\n\t"
        "@P bra DONE_%=;\n\t"
        "bra WAIT_%=;\n\t"
        "DONE_%=:\n\t"
        "}" :: "r"(mb), "r"(0) : "memory");

    // ---- extract all depths to registers (buffer will be overwritten) ----
    float d[CHUNKS];
    #pragma unroll
    for (int i = 0; i < CHUNKS; i++) {
        d[i] = s_buf[4 * (i * THREADS + t) + 3];
    }
    __syncthreads();   // all reads done before any xyz overwrite

    #pragma unroll
    for (int i = 0; i < CHUNKS; i++) {
        int p = i * THREADS + t;
        s_buf[3 * p + 0] =  d[i] * c;
        s_buf[3 * p + 1] = -d[i] * s;
        s_buf[3 * p + 2] =  d[i] * sp;
        // advance yaw by 256 columns (pi/16 Givens rotation)
        float cn = fmaf(c, ROT_C, -s * ROT_S);
        float sn = fmaf(s, ROT_C,  c * ROT_S);
        c = cn; s = sn;
    }

    __syncthreads();

    if (t == 0) {
        asm volatile("fence.proxy.async.shared::cta;" ::: "memory");
        uint32_t srcp = smem_u32(s_buf);
        const float* dstp = out + blockBase * 3;
        asm volatile(
            "cp.async.bulk.global.shared::cta.bulk_group [%0], [%1], %2;"
            :: "l"(dstp), "r"(srcp), "n"(OUT_BYTES_PER_BLOCK) : "memory");
        asm volatile("cp.async.bulk.commit_group;" ::: "memory");
        // keep smem alive until the TMA has read it
        asm volatile("cp.async.bulk.wait_group.read 0;" ::: "memory");
    }
}

extern "C" void kernel_launch(void* const* d_in, const int* in_sizes, int n_in,
                              void* d_out, int out_size) {
    const float* img = (const float*)d_in[0];
    float* out = (float*)d_out;
    proj_to_pointcloud_kernel<<<NBLOCKS, THREADS>>>(img, out);
}

// round 9
// speedup vs baseline: 1.0035x; 1.0035x over previous
#include <cuda_runtime.h>
#include <cstdint>

#define W 8192
#define H 2048
#define NPIX (W * H)
#define THREADS 256
#define PX_PER_BLOCK 2048
#define CHUNKS (PX_PER_BLOCK / THREADS)          // 8
#define NBLOCKS (NPIX / PX_PER_BLOCK)            // 8192
#define IMG_BYTES_PER_BLOCK (PX_PER_BLOCK * 16)  // 32768
#define OUT_BYTES_PER_BLOCK (PX_PER_BLOCK * 12)  // 24576

#define FOV_SPAN     0.5235987755982988f
#define FOV_ABS_DOWN 0.2617993877991494f
#define TWO_PI       6.283185307179586f
#define PI_F         3.141592653589793f

// Rotation by 256 column steps: delta = 256 * 2*pi/8192 = pi/16
#define ROT_C 0.9807852804032304f
#define ROT_S 0.1950903220161283f

__device__ __forceinline__ uint32_t smem_u32(const void* p) {
    uint32_t a;
    asm("{ .reg .u64 t; cvta.to.shared.u64 t, %1; cvt.u32.u64 %0, t; }"
        : "=r"(a) : "l"(p));
    return a;
}

// R8 structure + L2 evict_first policies on both bulk streams:
//   - load stream (256 MB, zero reuse) stops holding L2 capacity
//   - store stream's dirty lines drain to DRAM DURING the kernel instead of
//     piling up as a post-kernel writeback backlog that each graph replay
//     inherits (the invariant 7.3us total-kernel gap).
__global__ void __launch_bounds__(THREADS)
proj_to_pointcloud_kernel(const float* __restrict__ img, float* __restrict__ out) {
    __shared__ alignas(128) float s_buf[PX_PER_BLOCK * 4];   // 32 KB, dual-use
    __shared__ alignas(8)   uint64_t s_mbar;

    int t = threadIdx.x;
    long blockBase = (long)blockIdx.x * PX_PER_BLOCK;
    int row = (int)(blockBase >> 13);
    int j0  = (int)(blockBase & (W - 1));
    uint32_t mb = smem_u32(&s_mbar);

    uint64_t pol;
    asm("createpolicy.fractional.L2::evict_first.b64 %0, 1.0;" : "=l"(pol));

    if (t == 0) {
        asm volatile("mbarrier.init.shared.b64 [%0], %1;" :: "r"(mb), "r"(1));
    }
    __syncthreads();

    if (t == 0) {
        asm volatile("mbarrier.arrive.expect_tx.shared.b64 _, [%0], %1;"
                     :: "r"(mb), "r"(IMG_BYTES_PER_BLOCK) : "memory");
        uint32_t dstp = smem_u32(s_buf);
        const float* srcp = img + (blockBase << 2);
        asm volatile(
            "cp.async.bulk.shared::cta.global.mbarrier::complete_tx::bytes.L2::cache_hint "
            "[%0], [%1], %2, [%3], %4;"
            :: "r"(dstp), "l"(srcp), "n"(IMG_BYTES_PER_BLOCK), "r"(mb), "l"(pol)
            : "memory");
    }

    // ---- trig, overlapped with the TMA load ----
    float yaw = (float)(j0 + t) * (TWO_PI / (float)W) - PI_F;
    float s, c;
    sincosf(yaw, &s, &c);
    float pitch = (1.0f - (float)row / (float)H) * FOV_SPAN - FOV_ABS_DOWN;
    float sp = sinf(pitch);

    // ---- wait for image tile ----
    asm volatile(
        "{\n\t"
        ".reg .pred P;\n\t"
        "WAIT_%=:\n\t"
        "mbarrier.try_wait.parity.acquire.cta.shared::cta.b64 P, [%0], %1, 0x989680;\n\t"
        "@P bra DONE_%=;\n\t"
        "bra WAIT_%=;\n\t"
        "DONE_%=:\n\t"
        "}" :: "r"(mb), "r"(0) : "memory");

    // ---- extract depths to registers (buffer gets overwritten next) ----
    float d[CHUNKS];
    #pragma unroll
    for (int i = 0; i < CHUNKS; i++) {
        d[i] = s_buf[4 * (i * THREADS + t) + 3];
    }
    __syncthreads();   // all reads done before any xyz overwrite

    #pragma unroll
    for (int i = 0; i < CHUNKS; i++) {
        int p = i * THREADS + t;
        s_buf[3 * p + 0] =  d[i] * c;
        s_buf[3 * p + 1] = -d[i] * s;
        s_buf[3 * p + 2] =  d[i] * sp;
        // advance yaw by 256 columns (pi/16 Givens rotation)
        float cn = fmaf(c, ROT_C, -s * ROT_S);
        float sn = fmaf(s, ROT_C,  c * ROT_S);
        c = cn; s = sn;
    }

    __syncthreads();

    if (t == 0) {
        asm volatile("fence.proxy.async.shared::cta;" ::: "memory");
        uint32_t srcp = smem_u32(s_buf);
        const float* dstp = out + blockBase * 3;
        asm volatile(
            "cp.async.bulk.global.shared::cta.bulk_group.L2::cache_hint "
            "[%0], [%1], %2, %3;"
            :: "l"(dstp), "r"(srcp), "n"(OUT_BYTES_PER_BLOCK), "l"(pol)
            : "memory");
        asm volatile("cp.async.bulk.commit_group;" ::: "memory");
        // keep smem alive until the TMA has read it
        asm volatile("cp.async.bulk.wait_group.read 0;" ::: "memory");
    }
}

extern "C" void kernel_launch(void* const* d_in, const int* in_sizes, int n_in,
                              void* d_out, int out_size) {
    const float* img = (const float*)d_in[0];
    float* out = (float*)d_out;
    proj_to_pointcloud_kernel<<<NBLOCKS, THREADS>>>(img, out);
}